// round 1
// baseline (speedup 1.0000x reference)
#include <cuda_runtime.h>
#include <cuda_fp16.h>
#include <cstdint>
#include <cstddef>

#define BATCH 8192
#define IN_F  1024
#define OUT_F 1024

// ---------------- scratch (static device globals; no allocation) ----------------
__device__ __half   g_x16[BATCH * IN_F];   // fp16 copy of x (16 MB)
__device__ __half   g_H[IN_F * OUT_F];     // folded weight matrix H = (G_eff - b)/a (2 MB)
__device__ float    g_gbar[IN_F];          // mean_j G_quant[i,j]
__device__ float    g_geffbar[IN_F];       // mean_j G_eff[i,j]
__device__ float    g_corr[BATCH];         // per-row correction factor
__device__ unsigned g_minmax[2];           // monotone-mapped min/max of weight

// ---------------- helpers ----------------
__device__ __forceinline__ unsigned fmap(float f) {
    unsigned u = __float_as_uint(f);
    return (u & 0x80000000u) ? ~u : (u | 0x80000000u);
}
__device__ __forceinline__ float funmap(unsigned m) {
    unsigned u = (m & 0x80000000u) ? (m ^ 0x80000000u) : ~m;
    return __uint_as_float(u);
}

__global__ void k_init() {
    g_minmax[0] = 0xFFFFFFFFu;   // running min (mapped space)
    g_minmax[1] = 0u;            // running max (mapped space)
}

// grid-stride min/max over all weight elements (min/max are exact regardless of order)
__global__ void k_minmax(const float* __restrict__ w, int n) {
    unsigned lmin = 0xFFFFFFFFu, lmax = 0u;
    for (int i = blockIdx.x * blockDim.x + threadIdx.x; i < n; i += gridDim.x * blockDim.x) {
        unsigned m = fmap(w[i]);
        lmin = min(lmin, m);
        lmax = max(lmax, m);
    }
#pragma unroll
    for (int o = 16; o; o >>= 1) {
        lmin = min(lmin, __shfl_xor_sync(0xFFFFFFFFu, lmin, o));
        lmax = max(lmax, __shfl_xor_sync(0xFFFFFFFFu, lmax, o));
    }
    __shared__ unsigned smin[8], smax[8];
    int warp = threadIdx.x >> 5;
    if ((threadIdx.x & 31) == 0) { smin[warp] = lmin; smax[warp] = lmax; }
    __syncthreads();
    if (threadIdx.x == 0) {
        unsigned a = smin[0], b = smax[0];
        for (int i = 1; i < 8; i++) { a = min(a, smin[i]); b = max(b, smax[i]); }
        atomicMin(&g_minmax[0], a);
        atomicMax(&g_minmax[1], b);
    }
}

// fp32 -> fp16 conversion of x (vectorized, exact grid)
__global__ void k_convert_x(const float4* __restrict__ x) {
    int i = blockIdx.x * blockDim.x + threadIdx.x;
    float4 v = x[i];
    __half2* dst = reinterpret_cast<__half2*>(g_x16);
    dst[2 * i]     = __floats2half2_rn(v.x, v.y);
    dst[2 * i + 1] = __floats2half2_rn(v.z, v.w);
}

// Build H[i][j] = (G_eff - b)/a  (fp16), and per-i row means of G_quant / G_eff.
// One block per i (input index). Replicates jax fp32 op order via __f*_rn (no FMA fusion),
// rintf == round-half-to-even == jnp.round.
__global__ void k_build_h(const float* __restrict__ weight) {
    const int i = blockIdx.x;
    const int tid = threadIdx.x;
    const float Wmin = funmap(g_minmax[0]);
    const float Wmax = funmap(g_minmax[1]);
    const float Ghrs = (float)(1.0 / 1000000.0);
    const float span = (float)(1.0 / 1000.0 - 1.0 / 1000000.0);
    const float step = (float)((1.0 / 1000.0 - 1.0 / 1000000.0) / 15.0);
    const float denomW = __fsub_rn(Wmax, Wmin);
    const float a      = __fdiv_rn(span, denomW);
    const float bconst = __fsub_rn(Ghrs, __fmul_rn(a, Wmin));
    const float rowterm = (float)(IN_F - i);

    float s_g = 0.f, s_geff = 0.f;
    for (int j = tid; j < OUT_F; j += 256) {
        float w = weight[(size_t)j * IN_F + i];              // Wt[i][j] = weight[j][i]
        float u  = __fdiv_rn(__fsub_rn(w, Wmin), denomW);
        float G  = __fadd_rn(__fmul_rn(u, span), Ghrs);
        float q  = rintf(__fdiv_rn(__fsub_rn(G, Ghrs), step));
        float Gq = __fadd_rn(__fmul_rn(q, step), Ghrs);
        float rser = __fmul_rn(2.0f, __fadd_rn((float)(j + 1), rowterm));
        float Geff = __fdiv_rn(1.0f, __fadd_rn(__fdiv_rn(1.0f, Gq), rser));
        g_H[(size_t)i * OUT_F + j] = __float2half_rn(__fdiv_rn(__fsub_rn(Geff, bconst), a));
        s_g    += Gq;
        s_geff += Geff;
    }
    __shared__ float r0[256], r1[256];
    r0[tid] = s_g; r1[tid] = s_geff;
    __syncthreads();
    for (int o = 128; o > 0; o >>= 1) {
        if (tid < o) { r0[tid] += r0[tid + o]; r1[tid] += r1[tid + o]; }
        __syncthreads();
    }
    if (tid == 0) {
        g_gbar[i]    = r0[0] * (1.0f / 1024.0f);
        g_geffbar[i] = r1[0] * (1.0f / 1024.0f);
    }
}

// corr[b] = (x[b,:] . geffbar) / (x[b,:] . gbar)   (one warp per batch row)
__global__ void k_corr() {
    const int lane = threadIdx.x & 31;
    const int b = blockIdx.x * 8 + (threadIdx.x >> 5);
    const __half* xr = g_x16 + (size_t)b * IN_F;
    float num = 0.f, den = 0.f;
    for (int k = lane; k < IN_F; k += 32) {
        float xv = __half2float(xr[k]);
        num += xv * g_geffbar[k];
        den += xv * g_gbar[k];
    }
#pragma unroll
    for (int o = 16; o; o >>= 1) {
        num += __shfl_xor_sync(0xFFFFFFFFu, num, o);
        den += __shfl_xor_sync(0xFFFFFFFFu, den, o);
    }
    if (lane == 0) g_corr[b] = num / den;
}

// ---------------- fp16 tensor-core GEMM: out = x16 @ H + bias*corr ----------------
__device__ __forceinline__ void cp16(void* smem, const void* g) {
    unsigned s = (unsigned)__cvta_generic_to_shared(smem);
    asm volatile("cp.async.cg.shared.global [%0], [%1], 16;\n" :: "r"(s), "l"(g));
}
__device__ __forceinline__ void ldm_a(uint32_t* r, const void* p) {
    unsigned a = (unsigned)__cvta_generic_to_shared(p);
    asm volatile("ldmatrix.sync.aligned.m8n8.x4.shared.b16 {%0,%1,%2,%3}, [%4];\n"
                 : "=r"(r[0]), "=r"(r[1]), "=r"(r[2]), "=r"(r[3]) : "r"(a));
}
__device__ __forceinline__ void ldm_bt(uint32_t* r, const void* p) {
    unsigned a = (unsigned)__cvta_generic_to_shared(p);
    asm volatile("ldmatrix.sync.aligned.m8n8.x4.trans.shared.b16 {%0,%1,%2,%3}, [%4];\n"
                 : "=r"(r[0]), "=r"(r[1]), "=r"(r[2]), "=r"(r[3]) : "r"(a));
}
__device__ __forceinline__ void mma16816(float* d, const uint32_t* a, const uint32_t* b) {
    asm volatile("mma.sync.aligned.m16n8k16.row.col.f32.f16.f16.f32 "
                 "{%0,%1,%2,%3}, {%4,%5,%6,%7}, {%8,%9}, {%0,%1,%2,%3};\n"
                 : "+f"(d[0]), "+f"(d[1]), "+f"(d[2]), "+f"(d[3])
                 : "r"(a[0]), "r"(a[1]), "r"(a[2]), "r"(a[3]), "r"(b[0]), "r"(b[1]));
}

// BM=128, BN=128, BK=32, 256 threads (8 warps, 4x2), warp tile 32x64
__global__ __launch_bounds__(256, 2) void k_gemm(const float* __restrict__ bias,
                                                 float* __restrict__ out) {
    __shared__ __align__(16) __half As[2][128][40];   // +8 halfs pad -> conflict-free ldmatrix
    __shared__ __align__(16) __half Bs[2][32][136];

    const int bm = blockIdx.y * 128, bn = blockIdx.x * 128;
    const int tid = threadIdx.x, lane = tid & 31, warp = tid >> 5;
    const int wm = (warp >> 1) * 32, wn = (warp & 1) * 64;

    float acc[2][8][4];
#pragma unroll
    for (int a = 0; a < 2; a++)
#pragma unroll
        for (int b = 0; b < 8; b++)
#pragma unroll
            for (int c = 0; c < 4; c++) acc[a][b][c] = 0.f;

    const int arow = tid >> 2, acol = (tid & 3) * 8;   // A: 64 rows/pass, 2 passes
    const int brow = tid >> 4, bcol = (tid & 15) * 8;  // B: 16 rows/pass, 2 passes

#define LOAD_TILES(kt, s) do {                                                            \
        cp16(&As[s][arow][acol],      g_x16 + (size_t)(bm + arow) * IN_F + (kt) * 32 + acol);       \
        cp16(&As[s][arow + 64][acol], g_x16 + (size_t)(bm + arow + 64) * IN_F + (kt) * 32 + acol);  \
        cp16(&Bs[s][brow][bcol],      g_H + (size_t)((kt) * 32 + brow) * OUT_F + bn + bcol);        \
        cp16(&Bs[s][brow + 16][bcol], g_H + (size_t)((kt) * 32 + brow + 16) * OUT_F + bn + bcol);   \
        asm volatile("cp.async.commit_group;\n");                                          \
    } while (0)

    LOAD_TILES(0, 0);
    const int NK = IN_F / 32;   // 32 k-tiles
    for (int kt = 0; kt < NK; kt++) {
        const int s = kt & 1;
        if (kt + 1 < NK) {
            LOAD_TILES(kt + 1, s ^ 1);
            asm volatile("cp.async.wait_group 1;\n");
        } else {
            asm volatile("cp.async.wait_group 0;\n");
        }
        __syncthreads();
#pragma unroll
        for (int ks = 0; ks < 2; ks++) {
            const int k0 = ks * 16;
            uint32_t af[2][4];
#pragma unroll
            for (int mi = 0; mi < 2; mi++)
                ldm_a(af[mi], &As[s][wm + mi * 16 + (lane & 15)][k0 + ((lane >> 4) << 3)]);
            uint32_t bf[8][2];
#pragma unroll
            for (int nq = 0; nq < 4; nq++) {
                uint32_t r[4];
                ldm_bt(r, &Bs[s][k0 + (lane & 15)][wn + nq * 16 + ((lane & 16) >> 1)]);
                bf[2 * nq][0] = r[0]; bf[2 * nq][1] = r[1];
                bf[2 * nq + 1][0] = r[2]; bf[2 * nq + 1][1] = r[3];
            }
#pragma unroll
            for (int mi = 0; mi < 2; mi++)
#pragma unroll
                for (int ni = 0; ni < 8; ni++)
                    mma16816(acc[mi][ni], af[mi], bf[ni]);
        }
        __syncthreads();   // protect buffer s before it's overwritten two iterations later
    }
#undef LOAD_TILES

    // epilogue: out = acc + bias[col]*corr[row]
    const int g = lane >> 2, t = lane & 3;
#pragma unroll
    for (int mi = 0; mi < 2; mi++) {
        const int r0 = bm + wm + mi * 16 + g;
        const float c0 = g_corr[r0], c1 = g_corr[r0 + 8];
#pragma unroll
        for (int ni = 0; ni < 8; ni++) {
            const int c = bn + wn + ni * 8 + 2 * t;
            const float b0 = bias[c], b1 = bias[c + 1];
            float2 v0 = make_float2(acc[mi][ni][0] + b0 * c0, acc[mi][ni][1] + b1 * c0);
            float2 v1 = make_float2(acc[mi][ni][2] + b0 * c1, acc[mi][ni][3] + b1 * c1);
            *reinterpret_cast<float2*>(out + (size_t)r0 * OUT_F + c) = v0;
            *reinterpret_cast<float2*>(out + (size_t)(r0 + 8) * OUT_F + c) = v1;
        }
    }
}

// ---------------- launch ----------------
extern "C" void kernel_launch(void* const* d_in, const int* in_sizes, int n_in,
                              void* d_out, int out_size) {
    const float* x      = (const float*)d_in[0];   // [8192, 1024]
    const float* weight = (const float*)d_in[1];   // [1024, 1024]
    const float* bias   = (const float*)d_in[2];   // [1024]
    float* out = (float*)d_out;                    // [8192, 1024] fp32

    k_init<<<1, 32>>>();
    k_minmax<<<256, 256>>>(weight, OUT_F * IN_F);
    k_convert_x<<<(BATCH * IN_F / 4) / 256, 256>>>((const float4*)x);
    k_build_h<<<IN_F, 256>>>(weight);
    k_corr<<<BATCH / 8, 256>>>();
    dim3 grid(OUT_F / 128, BATCH / 128);
    k_gemm<<<grid, 256>>>(bias, out);
}